// round 8
// baseline (speedup 1.0000x reference)
#include <cuda_runtime.h>
#include <math.h>

#define B_ 64
#define D_ 512
#define N_ 1024
#define NH_ 8
#define DH_ 64
#define CCHUNKS_ 8          // k_dots c-split
#define CROWS_ (D_ / CCHUNKS_)

typedef unsigned long long u64;

__device__ __forceinline__ u64 pack2(float lo, float hi) {
    u64 r; asm("mov.b64 %0, {%1, %2};" : "=l"(r) : "f"(lo), "f"(hi)); return r;
}
__device__ __forceinline__ void unpack2(u64 v, float& lo, float& hi) {
    asm("mov.b64 {%0, %1}, %2;" : "=f"(lo), "=f"(hi) : "l"(v));
}
__device__ __forceinline__ void ffma2(u64& acc, u64 a, u64 b) {
    asm("fma.rn.f32x2 %0, %1, %2, %0;" : "+l"(acc) : "l"(a), "l"(b));
}

// Scratch (static device globals — no allocation allowed)
__device__ float g_qW[NH_][D_];                    // 16 KB
__device__ float g_qb[NH_];
__device__ float g_qpe[NH_][N_];                   // 32 KB
__device__ float g_dotsP[CCHUNKS_][B_][NH_][N_];   // 16 MB
__device__ float g_attn[B_][NH_][N_];              // 2 MB
__device__ float g_w[B_][NH_][D_];                 // 1 MB

// ---------------------------------------------------------------------------
// K0 (fused prep): blocks 0..15 -> qW/qb, blocks 16..47 -> qpe (fp32).
// ---------------------------------------------------------------------------
__global__ void k_prep(const float* __restrict__ q,
                       const float* __restrict__ Wkv,
                       const float* __restrict__ bkv) {
    if (blockIdx.x < 16) {
        int idx = blockIdx.x * 256 + threadIdx.x;   // 0..4095
        int h = idx >> 9;
        int c = idx & 511;
        const float4* qr = (const float4*)(q + h * DH_);
        const float4* wr = (const float4*)(Wkv + (size_t)c * 1024 + h * DH_);
        float acc = 0.f;
#pragma unroll
        for (int d4 = 0; d4 < DH_ / 4; d4++) {
            float4 qa = qr[d4], wa = wr[d4];
            acc = fmaf(qa.x, wa.x, acc);
            acc = fmaf(qa.y, wa.y, acc);
            acc = fmaf(qa.z, wa.z, acc);
            acc = fmaf(qa.w, wa.w, acc);
        }
        g_qW[h][c] = acc;
        if (idx < NH_) {
            float s = 0.f;
            for (int d = 0; d < DH_; d++)
                s = fmaf(q[idx * DH_ + d], bkv[idx * DH_ + d], s);
            g_qb[idx] = s;
        }
    } else {
        int idx = (blockIdx.x - 16) * 256 + threadIdx.x;  // 0..8191
        int h = idx >> 10;
        int n = idx & 1023;
        float acc = 0.f;
        float fn = (float)n;
#pragma unroll 8
        for (int i = 0; i < 32; i++) {
            float div = expf((float)(2 * i) * (-9.210340371976184f / 64.0f));
            float s, c;
            sincosf(fn * div, &s, &c);
            acc = fmaf(q[h * 64 + 2 * i], s, acc);
            acc = fmaf(q[h * 64 + 2 * i + 1], c, acc);
        }
        g_qpe[h][n] = acc;
    }
}

// ---------------------------------------------------------------------------
// K1: dots partials. grid = B*8 = 512 (b=bid>>3, chunk=bid&7), 256 threads.
// Thread t owns n = 4t..4t+3; f32x2 accumulators (ax,ay) and (az,aw) per head.
// qW pre-packed (w,w) in smem so each (c,h) is one LDS.64 + 2 FFMA2.
// ---------------------------------------------------------------------------
__global__ void __launch_bounds__(256, 4) k_dots(const float* __restrict__ x) {
    int chunk = blockIdx.x & 7;
    int b = blockIdx.x >> 3;
    int t = threadIdx.x;
    __shared__ float2 sQW2[CROWS_][8];   // (w,w) duplicated pairs, 4 KB
    int c0 = chunk * CROWS_;
    for (int i = t; i < CROWS_ * 8; i += 256) {
        int cl = i >> 3, h = i & 7;
        float v = g_qW[h][c0 + cl];
        sQW2[cl][h] = make_float2(v, v);
    }
    __syncthreads();

    const float4* X = (const float4*)(x + (size_t)b * D_ * N_ + (size_t)c0 * N_);
    const u64* sQ = (const u64*)sQW2;

    u64 axy[8], azw[8];
#pragma unroll
    for (int h = 0; h < 8; h++) { axy[h] = 0ull; azw[h] = 0ull; }

#pragma unroll 8
    for (int c = 0; c < CROWS_; c++) {
        float4 xv = X[c * 256 + t];
        u64 xlo = pack2(xv.x, xv.y);
        u64 xhi = pack2(xv.z, xv.w);
#pragma unroll
        for (int h = 0; h < 8; h++) {
            u64 w2 = sQ[c * 8 + h];    // broadcast LDS.64
            ffma2(axy[h], w2, xlo);
            ffma2(azw[h], w2, xhi);
        }
    }
    float4* dst = (float4*)&g_dotsP[chunk][b][0][0];
#pragma unroll
    for (int h = 0; h < 8; h++) {
        float ax, ay, az, aw;
        unpack2(axy[h], ax, ay);
        unpack2(azw[h], az, aw);
        dst[h * 256 + t] = make_float4(ax, ay, az, aw);
    }
}

// ---------------------------------------------------------------------------
// K2: softmax over n=1024 per (b,h). grid = 512, 256 threads (4 n each).
// ---------------------------------------------------------------------------
__global__ void k_softmax() {
    int b = blockIdx.x >> 3;
    int h = blockIdx.x & 7;
    int t = threadIdx.x;
    int lane = t & 31, wid = t >> 5;
    __shared__ float red[8];
    __shared__ float bcast;

    float4 pe = ((const float4*)&g_qpe[h][0])[t];
    float qb = g_qb[h];
    float z0 = pe.x + qb, z1 = pe.y + qb, z2 = pe.z + qb, z3 = pe.w + qb;
#pragma unroll
    for (int j = 0; j < CCHUNKS_; j++) {
        float4 p = ((const float4*)&g_dotsP[j][b][h][0])[t];
        z0 += p.x; z1 += p.y; z2 += p.z; z3 += p.w;
    }
    const float scale = 0.125f;  // 64^-0.5
    z0 *= scale; z1 *= scale; z2 *= scale; z3 *= scale;

    float m = fmaxf(fmaxf(z0, z1), fmaxf(z2, z3));
#pragma unroll
    for (int off = 16; off; off >>= 1)
        m = fmaxf(m, __shfl_xor_sync(0xffffffffu, m, off));
    if (lane == 0) red[wid] = m;
    __syncthreads();
    if (t == 0) {
        float mm = red[0];
#pragma unroll
        for (int i = 1; i < 8; i++) mm = fmaxf(mm, red[i]);
        bcast = mm;
    }
    __syncthreads();
    float M = bcast;

    float e0 = __expf(z0 - M), e1 = __expf(z1 - M);
    float e2 = __expf(z2 - M), e3 = __expf(z3 - M);
    float s = e0 + e1 + e2 + e3;
#pragma unroll
    for (int off = 16; off; off >>= 1)
        s += __shfl_xor_sync(0xffffffffu, s, off);
    if (lane == 0) red[wid] = s;
    __syncthreads();
    if (t == 0) {
        float ss = 0.f;
#pragma unroll
        for (int i = 0; i < 8; i++) ss += red[i];
        bcast = ss;
    }
    __syncthreads();
    float inv = 1.0f / bcast;

    ((float4*)&g_attn[b][h][0])[t] =
        make_float4(e0 * inv, e1 * inv, e2 * inv, e3 * inv);
}

// ---------------------------------------------------------------------------
// K3: w[b,h,c] = sum_n attn[b,h,n] * x[b,c,n].
// grid = 2048 (b=bid>>5, chunk=bid&31 of 16 c-rows), 256 threads.
// 2 c-rows per warp; f32x2 accumulator per (row,h) whose halves sum
// disjoint n and are added at the end. attn read from smem as b64.
// ---------------------------------------------------------------------------
__global__ void __launch_bounds__(256, 4) k_wsum(const float* __restrict__ x) {
    int b = blockIdx.x >> 5;
    int chunk = blockIdx.x & 31;
    int t = threadIdx.x;
    int lane = t & 31, wid = t >> 5;
    __shared__ float sAttn[NH_ * N_];   // 32 KB

    const float4* A = (const float4*)&g_attn[b][0][0];
    float4* sA4 = (float4*)sAttn;
    for (int i = t; i < NH_ * N_ / 4; i += 256) sA4[i] = A[i];
    __syncthreads();

    int cbase = chunk * 16 + wid * 2;
    const float* xb = x + (size_t)b * D_ * N_;
    const float4* r0 = (const float4*)(xb + (size_t)(cbase + 0) * N_);
    const float4* r1 = (const float4*)(xb + (size_t)(cbase + 1) * N_);
    const u64* sA8 = (const u64*)sAttn;

    u64 a0[8], a1[8];
#pragma unroll
    for (int i = 0; i < 8; i++) { a0[i] = 0ull; a1[i] = 0ull; }

#pragma unroll 4
    for (int k = 0; k < 8; k++) {
        int idx = lane + 32 * k;
        float4 x0 = r0[idx], x1 = r1[idx];
        u64 x0lo = pack2(x0.x, x0.y), x0hi = pack2(x0.z, x0.w);
        u64 x1lo = pack2(x1.x, x1.y), x1hi = pack2(x1.z, x1.w);
#pragma unroll
        for (int h = 0; h < 8; h++) {
            u64 alo = sA8[(h * 256 + idx) * 2 + 0];
            u64 ahi = sA8[(h * 256 + idx) * 2 + 1];
            ffma2(a0[h], alo, x0lo);
            ffma2(a0[h], ahi, x0hi);
            ffma2(a1[h], alo, x1lo);
            ffma2(a1[h], ahi, x1hi);
        }
    }

    // collapse f32x2 halves -> v[16] (v[h] row0, v[8+h] row1)
    float v[16];
#pragma unroll
    for (int h = 0; h < 8; h++) {
        float lo, hi;
        unpack2(a0[h], lo, hi); v[h] = lo + hi;
        unpack2(a1[h], lo, hi); v[8 + h] = lo + hi;
    }

    // Butterfly multi-value reduce: 16 values -> 1 per lane-pair.
#pragma unroll
    for (int i = 0; i < 8; i++) {
        float a = v[i], bb = v[i + 8];
        float mine = (lane & 16) ? bb : a;
        float send = (lane & 16) ? a : bb;
        v[i] = mine + __shfl_xor_sync(0xffffffffu, send, 16);
    }
#pragma unroll
    for (int i = 0; i < 4; i++) {
        float a = v[i], bb = v[i + 4];
        float mine = (lane & 8) ? bb : a;
        float send = (lane & 8) ? a : bb;
        v[i] = mine + __shfl_xor_sync(0xffffffffu, send, 8);
    }
#pragma unroll
    for (int i = 0; i < 2; i++) {
        float a = v[i], bb = v[i + 2];
        float mine = (lane & 4) ? bb : a;
        float send = (lane & 4) ? a : bb;
        v[i] = mine + __shfl_xor_sync(0xffffffffu, send, 4);
    }
    {
        float a = v[0], bb = v[1];
        float mine = (lane & 2) ? bb : a;
        float send = (lane & 2) ? a : bb;
        v[0] = mine + __shfl_xor_sync(0xffffffffu, send, 2);
    }
    v[0] += __shfl_xor_sync(0xffffffffu, v[0], 1);

    if (!(lane & 1)) {
        int i = lane >> 1;                 // 0..15: h = i&7, row = i>>3
        g_w[b][i & 7][cbase + (i >> 3)] = v[0];
    }
}

// ---------------------------------------------------------------------------
// K4: out[b][t] = sum_c w[b,h(t),c] * Wkv[c, 512+t] + bkv[512+t]
// grid = 64, 1024 threads: tid = half*512 + t; each half sums 256 c; smem add.
// ---------------------------------------------------------------------------
__global__ void k_out(const float* __restrict__ Wkv,
                      const float* __restrict__ bkv,
                      float* __restrict__ out) {
    int b = blockIdx.x;
    int tid = threadIdx.x;          // 0..1023
    int t = tid & 511;
    int half = tid >> 9;
    __shared__ float sw[NH_ * D_];   // 16 KB
    __shared__ float spart[512];
    const float4* W4 = (const float4*)&g_w[b][0][0];
    float4* s4 = (float4*)sw;
    for (int i = tid; i < NH_ * D_ / 4; i += 1024) s4[i] = W4[i];
    __syncthreads();

    int h = t >> 6;
    int c0 = half * 256;
    float acc = 0.f;
    const float* Wv = Wkv + 512 + t + (size_t)c0 * 1024;
    const float* swh = &sw[h * D_ + c0];
#pragma unroll 8
    for (int c = 0; c < 256; c++)
        acc = fmaf(swh[c], Wv[(size_t)c * 1024], acc);

    if (half) spart[t] = acc;
    __syncthreads();
    if (!half)
        out[b * 512 + t] = acc + spart[t] + bkv[512 + t];
}

// ---------------------------------------------------------------------------
extern "C" void kernel_launch(void* const* d_in, const int* in_sizes, int n_in,
                              void* d_out, int out_size) {
    const float* x   = (const float*)d_in[0];
    const float* q   = (const float*)d_in[1];
    const float* Wkv = (const float*)d_in[2];
    const float* bkv = (const float*)d_in[3];
    float* out = (float*)d_out;

    k_prep<<<48, 256>>>(q, Wkv, bkv);
    k_dots<<<B_ * CCHUNKS_, 256>>>(x);
    k_softmax<<<512, 256>>>();
    k_wsum<<<B_ * 32, 256>>>(x);
    k_out<<<64, 1024>>>(Wkv, bkv, out);
}